// round 3
// baseline (speedup 1.0000x reference)
#include <cuda_runtime.h>
#include <cstddef>

// CTC batch cost, prob-domain forward with exact power-of-two renormalization.
// One warp per batch element; lane l owns lattice states 4l..4l+3 (lane 31 also 128).
// B=512, T=512, C=128, L=64, S=129.
//
// Dynamic range: alpha is kept with warp max parked near 2^100; states remain
// representable down to 2^-149 (denormals), i.e. ~172 nats below the running
// max, vs 87 nats when normalizing to 1. Renorm scale factors are exact powers
// of two accumulated in an integer, so renormalization adds ZERO rounding.

#define CTC_B 512
#define CTC_T 512
#define CTC_C 128
#define CTC_L 64
#define PF 8  // prefetch depth == renorm period

__global__ __launch_bounds__(32)
void ctc_warp_kernel(const int* __restrict__ y_true,
                     const float* __restrict__ y_pred,
                     float* __restrict__ out)
{
    const int b    = blockIdx.x;
    const int lane = threadIdx.x;          // 0..31
    const unsigned FULL = 0xffffffffu;
    const float EPSF = 1e-7f;

    // Labels owned by this lane: k0 = 2*lane -> state 4l+1, k1 = 2*lane+1 -> state 4l+3
    const int c0 = y_true[b * CTC_L + 2 * lane];
    const int c1 = y_true[b * CTC_L + 2 * lane + 1];
    const int c1_prev = __shfl_up_sync(FULL, c1, 1);   // y[2l-1] lives in prev lane
    const bool skip1 = (lane > 0) && (c0 != c1_prev);  // state 4l+1: y[2l] != y[2l-1]
    const bool skip3 = (c1 != c0);                     // state 4l+3: y[2l+1] != y[2l]

    const float* row0 = y_pred + (size_t)b * CTC_T * CTC_C;

    // Virtual alpha_{-1} = (2^100, 0, 0, ...) at lane 0; true alpha = stored * 2^K.
    const float TWO100 = __int_as_float((100 + 127) << 23);  // 2^100
    float a0 = (lane == 0) ? TWO100 : 0.0f;
    float a1 = 0.0f, a2 = 0.0f, a3 = 0.0f, a4 = 0.0f;
    float pm1 = 0.0f;     // alpha_{t-1}[4l-1] (prev lane's a3), pipelined shfl
    int   K   = -100;     // integer log2 of the accumulated scale

    // Register prefetch buffers: blank col (broadcast), two label cols per lane.
    float fb[PF], f0[PF], f1[PF];
    #pragma unroll
    for (int j = 0; j < PF; ++j) {
        const float* r = row0 + j * CTC_C;
        fb[j] = __ldg(r + (CTC_C - 1));
        f0[j] = __ldg(r + c0);
        f1[j] = __ldg(r + c1);
    }

    for (int tb = 0; tb < CTC_T; tb += PF) {
        #pragma unroll
        for (int j = 0; j < PF; ++j) {
            const float pb = fb[j] + EPSF;
            const float p0 = f0[j] + EPSF;
            const float p1 = f1[j] + EPSF;

            // Prefetch t + PF (clamped; tail loads are redundant but harmless)
            int tn = tb + j + PF;
            if (tn > CTC_T - 1) tn = CTC_T - 1;
            const float* r = row0 + (size_t)tn * CTC_C;
            fb[j] = __ldg(r + (CTC_C - 1));
            f0[j] = __ldg(r + c0);
            f1[j] = __ldg(r + c1);

            // new[s] = p[s] * (a[s] + a[s-1] + skip*a[s-2]); states 4l..4l+3 (+128)
            const float n3 = p1 * ((a2 + (skip3 ? a1 : 0.0f)) + a3);   // s=4l+3 (label k1)
            const float n2 = pb * (a1 + a2);                           // s=4l+2 (blank)
            const float sh = __shfl_up_sync(FULL, n3, 1);              // next step's alpha[4l-1]
            const float n0 = pb * (a0 + pm1);                          // s=4l   (blank)
            const float n1 = p0 * ((a0 + (skip1 ? pm1 : 0.0f)) + a1);  // s=4l+1 (label k0)
            const float n4 = (lane == 31) ? pb * (a3 + a4) : 0.0f;     // s=128  (last blank)

            pm1 = (lane == 0) ? 0.0f : sh;
            a0 = n0; a1 = n1; a2 = n2; a3 = n3; a4 = n4;
        }

        // Exact renorm every PF steps: warp max via redux (bits order-preserving
        // for non-negative floats), round down to 2^k, rescale so max sits in
        // [2^100, 2^101). Scale factor 2^(100-k) applied as two exact power-of-2
        // multiplies (each factor's exponent stays in range); K accumulates the
        // exact integer log2 of the total scale.
        float m = fmaxf(fmaxf(fmaxf(a0, a1), fmaxf(a2, a3)), a4);
        m = __uint_as_float(__reduce_max_sync(FULL, __float_as_uint(m)));
        const int k = (int)((__float_as_uint(m) >> 23) & 0xff) - 127;  // floor(log2 m)
        K += k - 100;
        const float s1 = __int_as_float((127 - k) << 23);  // 2^-k   (exact)
        const float s2 = TWO100;                           // 2^100  (exact)
        a0 = a0 * s1 * s2;
        a1 = a1 * s1 * s2;
        a2 = a2 * s1 * s2;
        a3 = a3 * s1 * s2;
        a4 = a4 * s1 * s2;
        pm1 = pm1 * s1 * s2;
    }

    // ll = log(alpha_T[S-2] + alpha_T[S-1]) + K*ln2 ; states 127,128 live in lane 31.
    if (lane == 31) {
        out[b] = -(logf(a3 + a4) + (float)K * 0.693147180559945309f);
    }
}

extern "C" void kernel_launch(void* const* d_in, const int* in_sizes, int n_in,
                              void* d_out, int out_size)
{
    // Resolve inputs by size (y_true: 512*64 int32, y_pred: 512*512*128 float32).
    const void* p0 = d_in[0];
    const void* p1 = d_in[1];
    const int* y_true;
    const float* y_pred;
    if (in_sizes[0] == CTC_B * CTC_L) {
        y_true = (const int*)p0;
        y_pred = (const float*)p1;
    } else {
        y_true = (const int*)p1;
        y_pred = (const float*)p0;
    }
    float* out = (float*)d_out;

    ctc_warp_kernel<<<CTC_B, 32>>>(y_true, y_pred, out);
}

// round 4
// speedup vs baseline: 1.6970x; 1.6970x over previous
#include <cuda_runtime.h>
#include <cstddef>

// CTC batch cost, prob-domain forward with exact power-of-two renormalization.
// One warp per batch element; lane l owns lattice states 4l..4l+3 (lane 31 also 128).
// Rows of y_pred are streamed coalesced into a shared-memory ring via cp.async
// (3-chunk prefetch distance); label gathers are LDS from the ring.
// B=512, T=512, C=128, L=64, S=129.

#define CTC_B 512
#define CTC_T 512
#define CTC_C 128
#define CTC_L 64
#define CHUNK 8                    // steps per chunk == renorm period
#define NCHUNK (CTC_T / CHUNK)     // 64
#define DIST 3                     // chunks in flight (prefetch distance)
#define DROWS (CHUNK * DIST)       // 24 ring rows = 12 KB

__global__ __launch_bounds__(32)
void ctc_warp_kernel(const int* __restrict__ y_true,
                     const float* __restrict__ y_pred,
                     float* __restrict__ out)
{
    __shared__ float ring[DROWS * CTC_C];

    const int b    = blockIdx.x;
    const int lane = threadIdx.x;          // 0..31
    const unsigned FULL = 0xffffffffu;
    const float EPSF = 1e-7f;

    // Labels owned by this lane: k0 = 2*lane -> state 4l+1, k1 = 2*lane+1 -> state 4l+3
    const int c0 = y_true[b * CTC_L + 2 * lane];
    const int c1 = y_true[b * CTC_L + 2 * lane + 1];
    const int c1_prev = __shfl_up_sync(FULL, c1, 1);   // y[2l-1] lives in prev lane
    const bool skip1 = (lane > 0) && (c0 != c1_prev);  // state 4l+1: y[2l] != y[2l-1]
    const bool skip3 = (c1 != c0);                     // state 4l+3: y[2l+1] != y[2l]

    const float* row0 = y_pred + (size_t)b * CTC_T * CTC_C;

    // cp.async one full row (512B) coalesced: lane takes 16B at offset lane*16.
    const unsigned ring_base = (unsigned)__cvta_generic_to_shared(ring);
    auto load_chunk = [&](int c) {   // loads rows c*CHUNK .. c*CHUNK+7 into slots (c%DIST)*CHUNK+
        const int sbase = (c % DIST) * CHUNK;
        #pragma unroll
        for (int j = 0; j < CHUNK; ++j) {
            const int t = c * CHUNK + j;
            if (t < CTC_T) {
                unsigned dst = ring_base + (unsigned)(((sbase + j) * CTC_C + lane * 4) * 4);
                const float* src = row0 + (size_t)t * CTC_C + lane * 4;
                asm volatile("cp.async.cg.shared.global [%0], [%1], 16;\n"
                             :: "r"(dst), "l"(src));
            }
        }
        asm volatile("cp.async.commit_group;\n" ::: "memory");
    };

    // Prologue: DIST chunks in flight.
    for (int c = 0; c < DIST; ++c) load_chunk(c);

    // Virtual alpha_{-1} = (2^100, 0, 0, ...) at lane 0; true alpha = stored * 2^K.
    const float TWO100 = __int_as_float((100 + 127) << 23);  // 2^100
    float a0 = (lane == 0) ? TWO100 : 0.0f;
    float a1 = 0.0f, a2 = 0.0f, a3 = 0.0f, a4 = 0.0f;
    float pm1 = 0.0f;     // alpha_{t-1}[4l-1] (prev lane's a3), pipelined shfl
    int   K   = -100;     // integer log2 of the accumulated scale

    for (int c = 0; c < NCHUNK; ++c) {
        // Oldest group (this chunk's rows) must be complete; <= DIST-1 pending.
        asm volatile("cp.async.wait_group %0;\n" :: "n"(DIST - 1) : "memory");
        __syncwarp();

        const int sbase = (c % DIST) * CHUNK;
        #pragma unroll
        for (int j = 0; j < CHUNK; ++j) {
            const float* rs = ring + (sbase + j) * CTC_C;
            const float pb = rs[CTC_C - 1] + EPSF;  // broadcast LDS
            const float p0 = rs[c0] + EPSF;         // scattered LDS
            const float p1 = rs[c1] + EPSF;

            // new[s] = p[s] * (a[s] + a[s-1] + skip*a[s-2]); states 4l..4l+3 (+128)
            const float n3 = p1 * ((a2 + (skip3 ? a1 : 0.0f)) + a3);   // s=4l+3 (label k1)
            const float n2 = pb * (a1 + a2);                           // s=4l+2 (blank)
            const float sh = __shfl_up_sync(FULL, n3, 1);              // next step's alpha[4l-1]
            const float n0 = pb * (a0 + pm1);                          // s=4l   (blank)
            const float n1 = p0 * ((a0 + (skip1 ? pm1 : 0.0f)) + a1);  // s=4l+1 (label k0)
            const float n4 = (lane == 31) ? pb * (a3 + a4) : 0.0f;     // s=128  (last blank)

            pm1 = (lane == 0) ? 0.0f : sh;
            a0 = n0; a1 = n1; a2 = n2; a3 = n3; a4 = n4;
        }

        // All lanes finished reading this chunk's slots before refilling them.
        __syncwarp();
        load_chunk(c + DIST);

        // Exact renorm: warp max via redux (bits order-preserving for non-negative
        // floats), round down to 2^k, rescale so max sits in [2^100, 2^101).
        // Scale 2^(100-k) applied as two exact power-of-2 multiplies; K accumulates
        // the exact integer log2 of the total scale (zero rounding added).
        float m = fmaxf(fmaxf(fmaxf(a0, a1), fmaxf(a2, a3)), a4);
        m = __uint_as_float(__reduce_max_sync(FULL, __float_as_uint(m)));
        const int k = (int)((__float_as_uint(m) >> 23) & 0xff) - 127;  // floor(log2 m)
        K += k - 100;
        const float s1 = __int_as_float((127 - k) << 23);  // 2^-k   (exact)
        a0 = a0 * s1 * TWO100;
        a1 = a1 * s1 * TWO100;
        a2 = a2 * s1 * TWO100;
        a3 = a3 * s1 * TWO100;
        a4 = a4 * s1 * TWO100;
        pm1 = pm1 * s1 * TWO100;
    }

    // ll = log(alpha_T[S-2] + alpha_T[S-1]) + K*ln2 ; states 127,128 live in lane 31.
    if (lane == 31) {
        out[b] = -(logf(a3 + a4) + (float)K * 0.693147180559945309f);
    }
}

extern "C" void kernel_launch(void* const* d_in, const int* in_sizes, int n_in,
                              void* d_out, int out_size)
{
    // Resolve inputs by size (y_true: 512*64 int32, y_pred: 512*512*128 float32).
    const void* p0 = d_in[0];
    const void* p1 = d_in[1];
    const int* y_true;
    const float* y_pred;
    if (in_sizes[0] == CTC_B * CTC_L) {
        y_true = (const int*)p0;
        y_pred = (const float*)p1;
    } else {
        y_true = (const int*)p1;
        y_pred = (const float*)p0;
    }
    float* out = (float*)d_out;

    ctc_warp_kernel<<<CTC_B, 32>>>(y_true, y_pred, out);
}

// round 5
// speedup vs baseline: 1.8537x; 1.0923x over previous
#include <cuda_runtime.h>
#include <cstddef>

// CTC batch cost, prob-domain forward with exact power-of-two renormalization.
// One warp per batch element; lane l owns lattice states 4l..4l+3 (lane 31 also 128).
// Rows of y_pred are streamed coalesced into an 8-slot shared-memory ring via
// cp.async (prefetch distance 7 chunks = 28 KB in flight per warp); label
// gathers are LDS from the ring. B=512, T=512, C=128, L=64, S=129.

#define CTC_B 512
#define CTC_T 512
#define CTC_C 128
#define CTC_L 64
#define CHUNK 8                    // steps per chunk == renorm period
#define NCHUNK (CTC_T / CHUNK)     // 64
#define DIST 7                     // chunk-groups kept in flight
#define SLOTS 8                    // ring slots (DIST+1 decouples refill/consume)
#define DROWS (CHUNK * SLOTS)      // 64 ring rows = 32 KB

__global__ __launch_bounds__(32)
void ctc_warp_kernel(const int* __restrict__ y_true,
                     const float* __restrict__ y_pred,
                     float* __restrict__ out)
{
    __shared__ float ring[DROWS * CTC_C];

    const int b    = blockIdx.x;
    const int lane = threadIdx.x;          // 0..31
    const unsigned FULL = 0xffffffffu;
    const float EPSF = 1e-7f;

    // Labels owned by this lane: k0 = 2*lane -> state 4l+1, k1 = 2*lane+1 -> state 4l+3
    const int c0 = y_true[b * CTC_L + 2 * lane];
    const int c1 = y_true[b * CTC_L + 2 * lane + 1];
    const int c1_prev = __shfl_up_sync(FULL, c1, 1);   // y[2l-1] lives in prev lane
    const bool skip1 = (lane > 0) && (c0 != c1_prev);  // state 4l+1: y[2l] != y[2l-1]
    const bool skip3 = (c1 != c0);                     // state 4l+3: y[2l+1] != y[2l]

    const float* row0 = y_pred + (size_t)b * CTC_T * CTC_C;

    // cp.async one full row (512B) coalesced: lane takes 16B at offset lane*16.
    const unsigned ring_base = (unsigned)__cvta_generic_to_shared(ring);
    auto load_chunk = [&](int c) {   // rows c*CHUNK.. into ring slot c%SLOTS
        const int sbase = (c % SLOTS) * CHUNK;
        if (c < NCHUNK) {
            #pragma unroll
            for (int j = 0; j < CHUNK; ++j) {
                const int t = c * CHUNK + j;
                unsigned dst = ring_base + (unsigned)(((sbase + j) * CTC_C + lane * 4) * 4);
                const float* src = row0 + (size_t)t * CTC_C + lane * 4;
                asm volatile("cp.async.cg.shared.global [%0], [%1], 16;\n"
                             :: "r"(dst), "l"(src));
            }
        }
        asm volatile("cp.async.commit_group;\n" ::: "memory");  // commit even if empty
    };

    // Prologue: DIST chunk-groups in flight.
    for (int c = 0; c < DIST; ++c) load_chunk(c);

    // Virtual alpha_{-1} = (2^100, 0, 0, ...) at lane 0; true alpha = stored * 2^K.
    const float TWO100 = __int_as_float((100 + 127) << 23);  // 2^100
    float a0 = (lane == 0) ? TWO100 : 0.0f;
    float a1 = 0.0f, a2 = 0.0f, a3 = 0.0f, a4 = 0.0f;
    float pm1 = 0.0f;     // alpha_{t-1}[4l-1] (prev lane's a3), pipelined shfl
    int   K   = -100;     // integer log2 of the accumulated scale

    for (int c = 0; c < NCHUNK; ++c) {
        // Issue group c+DIST first (writes the slot consumed at iteration c-1,
        // whose LDS reads completed a full iteration ago) — keeps DIST groups
        // in flight through the compute phase.
        load_chunk(c + DIST);

        // Group c must be complete; up to DIST newer groups stay pending.
        asm volatile("cp.async.wait_group %0;\n" :: "n"(DIST) : "memory");
        __syncwarp();   // cross-lane visibility of cp.async-written smem

        const int sbase = (c % SLOTS) * CHUNK;
        #pragma unroll
        for (int j = 0; j < CHUNK; ++j) {
            const float* rs = ring + (sbase + j) * CTC_C;
            const float pb = rs[CTC_C - 1] + EPSF;  // broadcast LDS
            const float p0 = rs[c0] + EPSF;         // scattered LDS
            const float p1 = rs[c1] + EPSF;

            // new[s] = p[s] * (a[s] + a[s-1] + skip*a[s-2]); states 4l..4l+3 (+128)
            const float n3 = p1 * ((a2 + (skip3 ? a1 : 0.0f)) + a3);   // s=4l+3 (label k1)
            const float n2 = pb * (a1 + a2);                           // s=4l+2 (blank)
            const float sh = __shfl_up_sync(FULL, n3, 1);              // next step's alpha[4l-1]
            const float n0 = pb * (a0 + pm1);                          // s=4l   (blank)
            const float n1 = p0 * ((a0 + (skip1 ? pm1 : 0.0f)) + a1);  // s=4l+1 (label k0)
            const float n4 = (lane == 31) ? pb * (a3 + a4) : 0.0f;     // s=128  (last blank)

            pm1 = (lane == 0) ? 0.0f : sh;
            a0 = n0; a1 = n1; a2 = n2; a3 = n3; a4 = n4;
        }

        // Exact renorm: warp max via redux (bits order-preserving for non-negative
        // floats), round down to 2^k, rescale so max sits in [2^100, 2^101).
        // Scale 2^(100-k) applied as two exact power-of-2 multiplies; K accumulates
        // the exact integer log2 of the total scale (zero rounding added).
        float m = fmaxf(fmaxf(fmaxf(a0, a1), fmaxf(a2, a3)), a4);
        m = __uint_as_float(__reduce_max_sync(FULL, __float_as_uint(m)));
        const int k = (int)((__float_as_uint(m) >> 23) & 0xff) - 127;  // floor(log2 m)
        K += k - 100;
        const float s1 = __int_as_float((127 - k) << 23);  // 2^-k   (exact)
        a0 = a0 * s1 * TWO100;
        a1 = a1 * s1 * TWO100;
        a2 = a2 * s1 * TWO100;
        a3 = a3 * s1 * TWO100;
        a4 = a4 * s1 * TWO100;
        pm1 = pm1 * s1 * TWO100;
    }

    // ll = log(alpha_T[S-2] + alpha_T[S-1]) + K*ln2 ; states 127,128 live in lane 31.
    if (lane == 31) {
        out[b] = -(logf(a3 + a4) + (float)K * 0.693147180559945309f);
    }
}

extern "C" void kernel_launch(void* const* d_in, const int* in_sizes, int n_in,
                              void* d_out, int out_size)
{
    // Resolve inputs by size (y_true: 512*64 int32, y_pred: 512*512*128 float32).
    const void* p0 = d_in[0];
    const void* p1 = d_in[1];
    const int* y_true;
    const float* y_pred;
    if (in_sizes[0] == CTC_B * CTC_L) {
        y_true = (const int*)p0;
        y_pred = (const float*)p1;
    } else {
        y_true = (const int*)p1;
        y_pred = (const float*)p0;
    }
    float* out = (float*)d_out;

    ctc_warp_kernel<<<CTC_B, 32>>>(y_true, y_pred, out);
}